// round 2
// baseline (speedup 1.0000x reference)
#include <cuda_runtime.h>
#include <cuda_bf16.h>
#include <math.h>

#define NT 64
#define NQ 256
#define NPK 100000
#define NE 262144
#define NN 16384
#define DS 64
#define DV 32
#define TEH 128
#define FF 160
#define EB 296
#define NTILES 8192
#define EDGE_SMEM 61440

__device__ float g_kfeat[NN * FF];
__device__ int   g_cnt[2 * NN];
__device__ float g_invcnt[2 * NN];
__device__ float g_qx[NN * 3];
__device__ float g_R[NT * 9];
__device__ float g_pre[2 * NT * 64];

__global__ void zero_kernel(float* __restrict__ out) {
    int i = blockIdx.x * blockDim.x + threadIdx.x;
    int st = gridDim.x * blockDim.x;
    for (int z = i; z < NN * FF; z += st) g_kfeat[z] = 0.0f;
    for (int z = i; z < 2 * NN; z += st) g_cnt[z] = 0;
    if (i < 2 * NT * 3) out[i] = 0.0f;
}

__global__ void hist_kernel(const int* __restrict__ ed0, const int* __restrict__ ed1) {
    int i = blockIdx.x * blockDim.x + threadIdx.x;
    int st = gridDim.x * blockDim.x;
    for (int e = i; e < NE; e += st) atomicAdd(&g_cnt[ed0[e]], 1);
    for (int e = i; e < NE; e += st) atomicAdd(&g_cnt[NN + ed1[e]], 1);
}

// One block per t: rotation matrix, time embedding, qemb, per-(s,t) layer-1 bias row,
// rotated+translated query positions, and inverse counts (grid-stride).
__global__ void prep_kernel(const float* __restrict__ Ts, const float* __restrict__ time_,
                            const float* __restrict__ query_x,
                            const float* __restrict__ W_qt, const float* __restrict__ b_qt,
                            const float* __restrict__ W1_r, const float* __restrict__ b1_r) {
    __shared__ float te[128];
    __shared__ float qemb[128];
    __shared__ float Rsh[9];
    __shared__ float tsh[3];
    int t = blockIdx.x;
    int tid = threadIdx.x;  // 128 threads
    float tv = time_[t];
    {
        int k = tid & 63;
        float f = __expf(-logf(10000.0f) * (float)k / 63.0f);
        float a = tv * f;
        te[tid] = (tid < 64) ? sinf(a) : cosf(a);
    }
    if (tid == 0) {
        float qw = Ts[t * 7 + 0], qa = Ts[t * 7 + 1], qb = Ts[t * 7 + 2], qc = Ts[t * 7 + 3];
        float nrm = rsqrtf(qw * qw + qa * qa + qb * qb + qc * qc);
        qw *= nrm; qa *= nrm; qb *= nrm; qc *= nrm;
        Rsh[0] = 1.0f - 2.0f * (qb * qb + qc * qc);
        Rsh[1] = 2.0f * (qa * qb - qw * qc);
        Rsh[2] = 2.0f * (qa * qc + qw * qb);
        Rsh[3] = 2.0f * (qa * qb + qw * qc);
        Rsh[4] = 1.0f - 2.0f * (qa * qa + qc * qc);
        Rsh[5] = 2.0f * (qb * qc - qw * qa);
        Rsh[6] = 2.0f * (qa * qc - qw * qb);
        Rsh[7] = 2.0f * (qb * qc + qw * qa);
        Rsh[8] = 1.0f - 2.0f * (qa * qa + qb * qb);
        tsh[0] = Ts[t * 7 + 4]; tsh[1] = Ts[t * 7 + 5]; tsh[2] = Ts[t * 7 + 6];
        #pragma unroll
        for (int i = 0; i < 9; i++) g_R[t * 9 + i] = Rsh[i];
    }
    __syncthreads();
    {   // qemb[o] = te @ W_qt + b_qt
        int o = tid;
        float acc = b_qt[o];
        for (int k = 0; k < 128; k++) acc += te[k] * W_qt[k * TEH + o];
        qemb[o] = acc;
    }
    __syncthreads();
    {   // pre[s][t][j] = qemb @ W1[8:] + b1
        int s = tid >> 6, j = tid & 63;
        float acc = b1_r[s * 64 + j];
        const float* w = W1_r + s * 136 * 64 + 8 * 64 + j;
        for (int i = 0; i < 128; i++) acc += qemb[i] * w[i * 64];
        g_pre[(s * NT + t) * 64 + j] = acc;
    }
    // rotated query positions
    for (int q = tid; q < NQ; q += blockDim.x) {
        float x = query_x[q * 3 + 0], y = query_x[q * 3 + 1], z = query_x[q * 3 + 2];
        int n = t * NQ + q;
        g_qx[n * 3 + 0] = Rsh[0] * x + Rsh[1] * y + Rsh[2] * z + tsh[0];
        g_qx[n * 3 + 1] = Rsh[3] * x + Rsh[4] * y + Rsh[5] * z + tsh[1];
        g_qx[n * 3 + 2] = Rsh[6] * x + Rsh[7] * y + Rsh[8] * z + tsh[2];
    }
    // inverse counts
    int gtid = t * blockDim.x + tid;
    int gst = gridDim.x * blockDim.x;
    for (int z = gtid; z < 2 * NN; z += gst)
        g_invcnt[z] = 1.0f / ((float)g_cnt[z] + 1e-8f);
}

// Fused per-edge: rbf -> layer1+silu -> (32x192x64 GEMM, W2 in smem, reg-blocked) ->
// message construction -> scaled atomic scatter into kfeat.
__global__ __launch_bounds__(256, 2) void edge_kernel(
    const float* __restrict__ kx0, const float* __restrict__ kf0,
    const float* __restrict__ kx1, const float* __restrict__ kf1,
    const int* __restrict__ es0, const int* __restrict__ ed0,
    const int* __restrict__ es1, const int* __restrict__ ed1,
    const float* __restrict__ W1_r, const float* __restrict__ W2_r,
    const float* __restrict__ b2_r) {
    extern __shared__ float sm[];
    float* W2s  = sm;            // 12288
    float* W1s  = W2s + 12288;   // 512
    float* As   = W1s + 512;     // 2048  (A[j][e], 64x32)
    float* rbs  = As + 2048;     // 288   (32x9 padded)
    float* dirs = rbs + 288;     // 96
    float* invs = dirs + 96;     // 32
    int*   srcs = (int*)(invs + 32);  // 32
    int*   dsts = srcs + 32;          // 32
    int*   tts  = dsts + 32;          // 32

    int tid = threadIdx.x;
    int s = (blockIdx.x >= EB) ? 1 : 0;
    int blk = blockIdx.x - s * EB;
    const float* kx = s ? kx1 : kx0;
    const float* kf = s ? kf1 : kf0;
    const int* es = s ? es1 : es0;
    const int* ed = s ? ed1 : ed0;

    for (int i = tid; i < 12288; i += 256) W2s[i] = W2_r[s * 12288 + i];
    for (int i = tid; i < 512; i += 256) W1s[i] = W1_r[s * (136 * 64) + i];

    int tx = tid & 31, ty = tid >> 5;
    float b2reg[6];
    #pragma unroll
    for (int m = 0; m < 6; m++) b2reg[m] = b2_r[s * 192 + tx + 32 * m];
    const float* preS = g_pre + s * NT * 64;
    const float* icS = g_invcnt + s * NN;

    for (int tile = blk; tile < NTILES; tile += EB) {
        __syncthreads();
        if (tid < 32) {  // phase 1: per-edge geometry + rbf
            int e = tile * 32 + tid;
            int src = es[e], dst = ed[e];
            float rx = kx[src * 3 + 0] - g_qx[dst * 3 + 0];
            float ry = kx[src * 3 + 1] - g_qx[dst * 3 + 1];
            float rz = kx[src * 3 + 2] - g_qx[dst * 3 + 2];
            float r = sqrtf(rx * rx + ry * ry + rz * rz);
            float ir = 1.0f / (r + 1e-8f);
            dirs[tid * 3 + 0] = rx * ir;
            dirs[tid * 3 + 1] = ry * ir;
            dirs[tid * 3 + 2] = rz * ir;
            #pragma unroll
            for (int i = 0; i < 8; i++) {
                float dcl = r - (4.0f / 7.0f) * (float)i;
                rbs[tid * 9 + i] = __expf(-dcl * dcl * 4.0f);
            }
            invs[tid] = icS[dst];
            srcs[tid] = src; dsts[tid] = dst; tts[tid] = dst >> 8;
        }
        __syncthreads();
        {   // phase 2: layer1 + silu into A[j][e]
            int e = tid & 31;
            int jb = (tid >> 5) << 3;
            float rb[8];
            #pragma unroll
            for (int i = 0; i < 8; i++) rb[i] = rbs[e * 9 + i];
            const float* prow = preS + tts[e] * 64;
            #pragma unroll
            for (int jj = 0; jj < 8; jj++) {
                int j = jb + jj;
                float h = __ldg(prow + j);
                #pragma unroll
                for (int i = 0; i < 8; i++) h += rb[i] * W1s[i * 64 + j];
                As[j * 32 + e] = h * (1.0f / (1.0f + __expf(-h)));
            }
        }
        __syncthreads();
        // phase 3: GEMM. thread (tx,ty): edges {ty+8m}, cols {tx+32m}
        float acc[4][6];
        #pragma unroll
        for (int me = 0; me < 4; me++)
            #pragma unroll
            for (int m = 0; m < 6; m++) acc[me][m] = b2reg[m];
        #pragma unroll 4
        for (int j = 0; j < 64; j++) {
            float a0 = As[j * 32 + ty];
            float a1 = As[j * 32 + ty + 8];
            float a2 = As[j * 32 + ty + 16];
            float a3 = As[j * 32 + ty + 24];
            float w[6];
            #pragma unroll
            for (int m = 0; m < 6; m++) w[m] = W2s[j * 192 + tx + 32 * m];
            #pragma unroll
            for (int m = 0; m < 6; m++) {
                acc[0][m] += a0 * w[m];
                acc[1][m] += a1 * w[m];
                acc[2][m] += a2 * w[m];
                acc[3][m] += a3 * w[m];
            }
        }
        // phase 4: message + atomic scatter (cols map exactly to semantic weights)
        #pragma unroll
        for (int me = 0; me < 4; me++) {
            int e = ty + 8 * me;
            int src = srcs[e], dst = dsts[e];
            float inv = invs[e];
            float dx = dirs[e * 3 + 0], dy = dirs[e * 3 + 1], dz = dirs[e * 3 + 2];
            const float* kfr = kf + (size_t)src * FF;
            float ks1 = __ldg(kfr + tx);
            float ks2 = __ldg(kfr + 32 + tx);
            float kvx = __ldg(kfr + 64 + 3 * tx + 0);
            float kvy = __ldg(kfr + 64 + 3 * tx + 1);
            float kvz = __ldg(kfr + 64 + 3 * tx + 2);
            float w00a = acc[me][0], w00b = acc[me][1], wvs = acc[me][2];
            float wsv = acc[me][3], wvvs = acc[me][4], wvvv = acc[me][5];
            float dot = kvx * dx + kvy * dy + kvz * dz;
            float ms1 = (w00a * ks1 + wvvs * dot) * inv;
            float ms2 = w00b * ks2 * inv;
            float crx = kvy * dz - kvz * dy;
            float cry = kvz * dx - kvx * dz;
            float crz = kvx * dy - kvy * dx;
            float t1 = wsv * ks1;
            float mvx = (wvs * kvx + t1 * dx + wvvv * crx) * inv;
            float mvy = (wvs * kvy + t1 * dy + wvvv * cry) * inv;
            float mvz = (wvs * kvz + t1 * dz + wvvv * crz) * inv;
            float* dstp = g_kfeat + (size_t)dst * FF;
            atomicAdd(dstp + tx, ms1);
            atomicAdd(dstp + 32 + tx, ms2);
            atomicAdd(dstp + 64 + 3 * tx + 0, mvx);
            atomicAdd(dstp + 64 + 3 * tx + 1, mvy);
            atomicAdd(dstp + 64 + 3 * tx + 2, mvz);
        }
    }
}

// Tensor-product heads + final weighted reduction. One warp per n, lane = channel.
__global__ __launch_bounds__(256) void tp_kernel(
    const float* __restrict__ query_f, const float* __restrict__ query_x,
    const float* __restrict__ query_w,
    const float* __restrict__ p00, const float* __restrict__ prest,
    const float* __restrict__ Ws_tp, const float* __restrict__ Wv_tp,
    float* __restrict__ out) {
    __shared__ float Wss[96 * 33];
    __shared__ float Wvs[96 * 32];
    __shared__ float s_sh[8][96];
    __shared__ float v_sh[8][96 * 3];
    __shared__ float accOut[6];
    int tid = threadIdx.x;
    int w = tid >> 5, c = tid & 31;
    int n = blockIdx.x * 8 + w;
    int t = n >> 8, q = n & 255;
    if (tid < 6) accOut[tid] = 0.0f;

    const float* kfr = g_kfeat + (size_t)n * FF;
    const float* qfr = query_f + (size_t)q * FF;
    float ks1 = kfr[c], ks2 = kfr[32 + c];
    float kvx = kfr[64 + 3 * c + 0], kvy = kfr[64 + 3 * c + 1], kvz = kfr[64 + 3 * c + 2];
    float qs1 = qfr[c], qs2 = qfr[32 + c];
    float qrx = qfr[64 + 3 * c + 0], qry = qfr[64 + 3 * c + 1], qrz = qfr[64 + 3 * c + 2];
    float R[9];
    #pragma unroll
    for (int i = 0; i < 9; i++) R[i] = __ldg(g_R + t * 9 + i);
    float qvx = R[0] * qrx + R[1] * qry + R[2] * qrz;
    float qvy = R[3] * qrx + R[4] * qry + R[5] * qrz;
    float qvz = R[6] * qrx + R[7] * qry + R[8] * qrz;

    float lin[3], ang[3];
    for (int head = 0; head < 2; head++) {
        __syncthreads();
        for (int i = tid; i < 96 * 33; i += 256) Wss[i] = Ws_tp[head * (96 * 33) + i];
        for (int i = tid; i < 96 * 32; i += 256) Wvs[i] = Wv_tp[head * (96 * 32) + i];
        __syncthreads();
        float p1 = __ldg(p00 + head * 64 + c);
        float p2 = __ldg(p00 + head * 64 + 32 + c);
        float pr0 = __ldg(prest + head * 128 + c);
        float pr1 = __ldg(prest + head * 128 + 32 + c);
        float pr2 = __ldg(prest + head * 128 + 64 + c);
        float pr3 = __ldg(prest + head * 128 + 96 + c);
        s_sh[w][c] = p1 * ks1 * qs1;
        s_sh[w][32 + c] = p2 * ks2 * qs2;
        s_sh[w][64 + c] = pr2 * (kvx * qvx + kvy * qvy + kvz * qvz);
        v_sh[w][3 * c + 0] = pr0 * kvx * qs1;
        v_sh[w][3 * c + 1] = pr0 * kvy * qs1;
        v_sh[w][3 * c + 2] = pr0 * kvz * qs1;
        v_sh[w][3 * (32 + c) + 0] = pr1 * ks1 * qvx;
        v_sh[w][3 * (32 + c) + 1] = pr1 * ks1 * qvy;
        v_sh[w][3 * (32 + c) + 2] = pr1 * ks1 * qvz;
        v_sh[w][3 * (64 + c) + 0] = pr3 * (kvy * qvz - kvz * qvy);
        v_sh[w][3 * (64 + c) + 1] = pr3 * (kvz * qvx - kvx * qvz);
        v_sh[w][3 * (64 + c) + 2] = pr3 * (kvx * qvy - kvy * qvx);
        __syncwarp();
        float sg = 0.0f, vmx = 0.0f, vmy = 0.0f, vmz = 0.0f;
        #pragma unroll 4
        for (int ch = 0; ch < 96; ch++) {
            float sv = s_sh[w][ch];
            sg += sv * Wss[ch * 33 + 1 + c];
            float wv = Wvs[ch * 32 + c];
            vmx += v_sh[w][3 * ch + 0] * wv;
            vmy += v_sh[w][3 * ch + 1] * wv;
            vmz += v_sh[w][3 * ch + 2] * wv;
        }
        float sig = 1.0f / (1.0f + __expf(-sg));
        float px = vmx * sig, py = vmy * sig, pz = vmz * sig;
        #pragma unroll
        for (int off = 16; off > 0; off >>= 1) {
            px += __shfl_xor_sync(0xffffffffu, px, off);
            py += __shfl_xor_sync(0xffffffffu, py, off);
            pz += __shfl_xor_sync(0xffffffffu, pz, off);
        }
        float sc = 1.0f / 32.0f;
        if (head == 0) { lin[0] = px * sc; lin[1] = py * sc; lin[2] = pz * sc; }
        else { ang[0] = px * sc; ang[1] = py * sc; ang[2] = pz * sc; }
        __syncwarp();
    }
    __syncthreads();
    if (c == 0) {
        // world frame = R^T v
        float lwx = R[0] * lin[0] + R[3] * lin[1] + R[6] * lin[2];
        float lwy = R[1] * lin[0] + R[4] * lin[1] + R[7] * lin[2];
        float lwz = R[2] * lin[0] + R[5] * lin[1] + R[8] * lin[2];
        float awx = R[0] * ang[0] + R[3] * ang[1] + R[6] * ang[2];
        float awy = R[1] * ang[0] + R[4] * ang[1] + R[7] * ang[2];
        float awz = R[2] * ang[0] + R[5] * ang[1] + R[8] * ang[2];
        float qx0 = query_x[q * 3 + 0], qx1 = query_x[q * 3 + 1], qx2 = query_x[q * 3 + 2];
        float ox = qx1 * lwz - qx2 * lwy;
        float oy = qx2 * lwx - qx0 * lwz;
        float oz = qx0 * lwy - qx1 * lwx;
        float ww = query_w[q];
        atomicAdd(&accOut[0], ww * (ox + awx));
        atomicAdd(&accOut[1], ww * (oy + awy));
        atomicAdd(&accOut[2], ww * (oz + awz));
        atomicAdd(&accOut[3], ww * lwx);
        atomicAdd(&accOut[4], ww * lwy);
        atomicAdd(&accOut[5], ww * lwz);
    }
    __syncthreads();
    if (tid < 6) {
        int tt = blockIdx.x >> 5;
        int idx = (tid < 3) ? (tt * 3 + tid) : (NT * 3 + tt * 3 + (tid - 3));
        atomicAdd(out + idx, accOut[tid]);
    }
}

extern "C" void kernel_launch(void* const* d_in, const int* in_sizes, int n_in,
                              void* d_out, int out_size) {
    const float* Ts      = (const float*)d_in[0];
    const float* time_   = (const float*)d_in[1];
    const float* query_x = (const float*)d_in[2];
    const float* query_f = (const float*)d_in[3];
    const float* query_w = (const float*)d_in[4];
    const float* kx0     = (const float*)d_in[5];
    const float* kf0     = (const float*)d_in[6];
    const float* kx1     = (const float*)d_in[7];
    const float* kf1     = (const float*)d_in[8];
    const int*   es0     = (const int*)d_in[9];
    const int*   ed0     = (const int*)d_in[10];
    const int*   es1     = (const int*)d_in[11];
    const int*   ed1     = (const int*)d_in[12];
    const float* W_qt    = (const float*)d_in[13];
    const float* b_qt    = (const float*)d_in[14];
    const float* W1_r    = (const float*)d_in[15];
    const float* b1_r    = (const float*)d_in[16];
    const float* W2_r    = (const float*)d_in[17];
    const float* b2_r    = (const float*)d_in[18];
    const float* p00     = (const float*)d_in[19];
    const float* prest   = (const float*)d_in[20];
    const float* Ws_tp   = (const float*)d_in[21];
    const float* Wv_tp   = (const float*)d_in[22];
    float* out = (float*)d_out;

    cudaFuncSetAttribute(edge_kernel, cudaFuncAttributeMaxDynamicSharedMemorySize, EDGE_SMEM);

    zero_kernel<<<2048, 256>>>(out);
    hist_kernel<<<1024, 256>>>(ed0, ed1);
    prep_kernel<<<NT, 128>>>(Ts, time_, query_x, W_qt, b_qt, W1_r, b1_r);
    edge_kernel<<<2 * EB, 256, EDGE_SMEM>>>(kx0, kf0, kx1, kf1,
                                            es0, ed0, es1, ed1,
                                            W1_r, W2_r, b2_r);
    tp_kernel<<<NN / 8, 256>>>(query_f, query_x, query_w, p00, prest, Ws_tp, Wv_tp, out);
}

// round 4
// speedup vs baseline: 1.1964x; 1.1964x over previous
#include <cuda_runtime.h>
#include <cuda_bf16.h>
#include <math.h>

#define NT 64
#define NQ 256
#define NPK 100000
#define NE 262144
#define NN 16384
#define DS 64
#define DV 32
#define TEH 128
#define FF 160
#define EB 296
#define TILES_PER_SCALE 4096
#define EDGE_SMEM 71680

__device__ float g_kfeat[NN * FF];
__device__ int   g_cnt[2 * NN];
__device__ int   g_cur[2 * NN];
__device__ float g_invcnt[2 * NN];
__device__ float g_qx[NN * 3];
__device__ float g_R[NT * 9];
__device__ float g_pre[2 * NT * 64];
__device__ int2  g_srt[2 * NE];

__global__ void zero_kernel(float* __restrict__ out) {
    int i = blockIdx.x * blockDim.x + threadIdx.x;
    int st = gridDim.x * blockDim.x;
    for (int z = i; z < NN * FF; z += st) g_kfeat[z] = 0.0f;
    for (int z = i; z < 2 * NN; z += st) g_cnt[z] = 0;
    if (i < 2 * NT * 3) out[i] = 0.0f;
}

__global__ void hist_kernel(const int* __restrict__ ed0, const int* __restrict__ ed1) {
    int i = blockIdx.x * blockDim.x + threadIdx.x;
    int st = gridDim.x * blockDim.x;
    for (int e = i; e < NE; e += st) atomicAdd(&g_cnt[ed0[e]], 1);
    for (int e = i; e < NE; e += st) atomicAdd(&g_cnt[NN + ed1[e]], 1);
}

// Exclusive scan of g_cnt[0..32767] into g_cur (single block, 1024 threads x 32).
__global__ void scan_kernel() {
    __shared__ int sm[1024];
    int tid = threadIdx.x;
    int base = tid * 32;
    int loc[32];
    int s = 0;
    #pragma unroll
    for (int i = 0; i < 32; i++) { loc[i] = g_cnt[base + i]; s += loc[i]; }
    sm[tid] = s;
    __syncthreads();
    for (int off = 1; off < 1024; off <<= 1) {
        int v = (tid >= off) ? sm[tid - off] : 0;
        __syncthreads();
        sm[tid] += v;
        __syncthreads();
    }
    int ex = sm[tid] - s;
    #pragma unroll
    for (int i = 0; i < 32; i++) { g_cur[base + i] = ex; ex += loc[i]; }
}

// Scatter edges into dst-sorted order. Scale-1 offsets naturally start at NE.
__global__ void scatter_kernel(const int* __restrict__ es0, const int* __restrict__ ed0,
                               const int* __restrict__ es1, const int* __restrict__ ed1) {
    int i = blockIdx.x * blockDim.x + threadIdx.x;
    int st = gridDim.x * blockDim.x;
    for (int e = i; e < NE; e += st) {
        int d = ed0[e];
        int pos = atomicAdd(&g_cur[d], 1);
        g_srt[pos] = make_int2(es0[e], d);
    }
    for (int e = i; e < NE; e += st) {
        int d = ed1[e];
        int pos = atomicAdd(&g_cur[NN + d], 1);
        g_srt[pos] = make_int2(es1[e], d);
    }
}

// One block per t: rotation matrix, time embedding, qemb, per-(s,t) layer-1 bias row,
// rotated+translated query positions, inverse counts.
__global__ void prep_kernel(const float* __restrict__ Ts, const float* __restrict__ time_,
                            const float* __restrict__ query_x,
                            const float* __restrict__ W_qt, const float* __restrict__ b_qt,
                            const float* __restrict__ W1_r, const float* __restrict__ b1_r) {
    __shared__ float te[128];
    __shared__ float qemb[128];
    __shared__ float Rsh[9];
    __shared__ float tsh[3];
    int t = blockIdx.x;
    int tid = threadIdx.x;  // 128 threads
    float tv = time_[t];
    {
        int k = tid & 63;
        float f = __expf(-logf(10000.0f) * (float)k / 63.0f);
        float a = tv * f;
        te[tid] = (tid < 64) ? sinf(a) : cosf(a);
    }
    if (tid == 0) {
        float qw = Ts[t * 7 + 0], qa = Ts[t * 7 + 1], qb = Ts[t * 7 + 2], qc = Ts[t * 7 + 3];
        float nrm = rsqrtf(qw * qw + qa * qa + qb * qb + qc * qc);
        qw *= nrm; qa *= nrm; qb *= nrm; qc *= nrm;
        Rsh[0] = 1.0f - 2.0f * (qb * qb + qc * qc);
        Rsh[1] = 2.0f * (qa * qb - qw * qc);
        Rsh[2] = 2.0f * (qa * qc + qw * qb);
        Rsh[3] = 2.0f * (qa * qb + qw * qc);
        Rsh[4] = 1.0f - 2.0f * (qa * qa + qc * qc);
        Rsh[5] = 2.0f * (qb * qc - qw * qa);
        Rsh[6] = 2.0f * (qa * qc - qw * qb);
        Rsh[7] = 2.0f * (qb * qc + qw * qa);
        Rsh[8] = 1.0f - 2.0f * (qa * qa + qb * qb);
        tsh[0] = Ts[t * 7 + 4]; tsh[1] = Ts[t * 7 + 5]; tsh[2] = Ts[t * 7 + 6];
        #pragma unroll
        for (int i = 0; i < 9; i++) g_R[t * 9 + i] = Rsh[i];
    }
    __syncthreads();
    {
        int o = tid;
        float acc = b_qt[o];
        for (int k = 0; k < 128; k++) acc += te[k] * W_qt[k * TEH + o];
        qemb[o] = acc;
    }
    __syncthreads();
    {
        int s = tid >> 6, j = tid & 63;
        float acc = b1_r[s * 64 + j];
        const float* w = W1_r + s * 136 * 64 + 8 * 64 + j;
        for (int i = 0; i < 128; i++) acc += qemb[i] * w[i * 64];
        g_pre[(s * NT + t) * 64 + j] = acc;
    }
    for (int q = tid; q < NQ; q += blockDim.x) {
        float x = query_x[q * 3 + 0], y = query_x[q * 3 + 1], z = query_x[q * 3 + 2];
        int n = t * NQ + q;
        g_qx[n * 3 + 0] = Rsh[0] * x + Rsh[1] * y + Rsh[2] * z + tsh[0];
        g_qx[n * 3 + 1] = Rsh[3] * x + Rsh[4] * y + Rsh[5] * z + tsh[1];
        g_qx[n * 3 + 2] = Rsh[6] * x + Rsh[7] * y + Rsh[8] * z + tsh[2];
    }
    int gtid = t * blockDim.x + tid;
    int gst = gridDim.x * blockDim.x;
    for (int z = gtid; z < 2 * NN; z += gst)
        g_invcnt[z] = 1.0f / ((float)g_cnt[z] + 1e-8f);
}

// Fused per-edge pipeline on dst-sorted edges, 64-edge tiles.
// Phase3 GEMM: 8 edges x 6 cols per thread, f32x2 packed FMAs (edges paired).
// Phase4: same-dst run merging before atomic flush.
__global__ __launch_bounds__(256, 2) void edge_kernel(
    const float* __restrict__ kx0, const float* __restrict__ kf0,
    const float* __restrict__ kx1, const float* __restrict__ kf1,
    const float* __restrict__ W1_r, const float* __restrict__ W2_r,
    const float* __restrict__ b2_r) {
    extern __shared__ float sm[];
    float* W2s  = sm;              // 12288
    float* As   = W2s + 12288;     // 4096  A[j][e], 64x64, 16B-aligned
    float* W1s  = As + 4096;       // 512
    float* rbs  = W1s + 512;       // 576   (64x9)
    float* dirs = rbs + 576;       // 192
    float* invs = dirs + 192;      // 64
    int*   srcs = (int*)(invs + 64);   // 64
    int*   dsts = srcs + 64;           // 64
    int*   tts  = dsts + 64;           // 64

    int tid = threadIdx.x;
    int s = (blockIdx.x >= EB) ? 1 : 0;
    int blk = blockIdx.x - s * EB;
    const float* kx = s ? kx1 : kx0;
    const float* kf = s ? kf1 : kf0;

    for (int i = tid; i < 12288; i += 256) W2s[i] = W2_r[s * 12288 + i];
    for (int i = tid; i < 512; i += 256) W1s[i] = W1_r[s * (136 * 64) + i];

    int tx = tid & 31, ty = tid >> 5;
    unsigned long long b2p[6];
    #pragma unroll
    for (int m = 0; m < 6; m++) {
        float b = b2_r[s * 192 + tx + 32 * m];
        asm("mov.b64 %0, {%1, %1};" : "=l"(b2p[m]) : "f"(b));
    }
    const float* preS = g_pre + s * NT * 64;
    const float* icS = g_invcnt + s * NN;
    const int2* srtS = g_srt + s * NE;

    int e2 = tid & 63;            // phase-2 edge
    int jb = (tid >> 6) * 16;     // phase-2 j group

    for (int tile = blk; tile < TILES_PER_SCALE; tile += EB) {
        __syncthreads();
        if (tid < 64) {  // phase 1: geometry + rbf (edges are dst-sorted)
            int2 sd = srtS[tile * 64 + tid];
            int src = sd.x, dst = sd.y;
            float rx = kx[src * 3 + 0] - g_qx[dst * 3 + 0];
            float ry = kx[src * 3 + 1] - g_qx[dst * 3 + 1];
            float rz = kx[src * 3 + 2] - g_qx[dst * 3 + 2];
            float r = sqrtf(rx * rx + ry * ry + rz * rz);
            float ir = 1.0f / (r + 1e-8f);
            dirs[tid * 3 + 0] = rx * ir;
            dirs[tid * 3 + 1] = ry * ir;
            dirs[tid * 3 + 2] = rz * ir;
            #pragma unroll
            for (int i = 0; i < 8; i++) {
                float dcl = r - (4.0f / 7.0f) * (float)i;
                rbs[tid * 9 + i] = __expf(-dcl * dcl * 4.0f);
            }
            invs[tid] = icS[dst];
            srcs[tid] = src; dsts[tid] = dst; tts[tid] = dst >> 8;
        }
        __syncthreads();
        {   // phase 2: layer1 + silu into A[j][e]  (16 j per thread)
            float rb[8];
            #pragma unroll
            for (int i = 0; i < 8; i++) rb[i] = rbs[e2 * 9 + i];
            const float* prow = preS + tts[e2] * 64;  // mostly warp-uniform (sorted)
            #pragma unroll
            for (int jj = 0; jj < 16; jj++) {
                int j = jb + jj;
                float h = __ldg(prow + j);
                #pragma unroll
                for (int i = 0; i < 8; i++) h += rb[i] * W1s[i * 64 + j];
                As[j * 64 + e2] = h * (1.0f / (1.0f + __expf(-h)));
            }
        }
        __syncthreads();
        // phase 3: GEMM. warp ty owns edges ty*8..ty*8+7; lane tx owns cols tx+32m.
        unsigned long long acc[4][6];
        #pragma unroll
        for (int k = 0; k < 4; k++)
            #pragma unroll
            for (int m = 0; m < 6; m++) acc[k][m] = b2p[m];
        #pragma unroll 2
        for (int j = 0; j < 64; j++) {
            const ulonglong2* Ar = reinterpret_cast<const ulonglong2*>(As + j * 64 + ty * 8);
            ulonglong2 p0 = Ar[0];
            ulonglong2 p1 = Ar[1];
            unsigned long long a0 = p0.x, a1 = p0.y, a2v = p1.x, a3 = p1.y;
            const float* wr = W2s + j * 192 + tx;
            #pragma unroll
            for (int m = 0; m < 6; m++) {
                float wv = wr[32 * m];
                unsigned long long ws;
                asm("mov.b64 %0, {%1, %1};" : "=l"(ws) : "f"(wv));
                asm("fma.rn.f32x2 %0, %1, %2, %0;" : "+l"(acc[0][m]) : "l"(a0), "l"(ws));
                asm("fma.rn.f32x2 %0, %1, %2, %0;" : "+l"(acc[1][m]) : "l"(a1), "l"(ws));
                asm("fma.rn.f32x2 %0, %1, %2, %0;" : "+l"(acc[2][m]) : "l"(a2v), "l"(ws));
                asm("fma.rn.f32x2 %0, %1, %2, %0;" : "+l"(acc[3][m]) : "l"(a3), "l"(ws));
            }
        }
        // phase 4: message + run-merged atomic scatter
        {
            float m0 = 0.f, m1 = 0.f, m2 = 0.f, m3 = 0.f, m4 = 0.f;
            float curinv = 0.f;
            int cur = -1;
            #pragma unroll
            for (int e8 = 0; e8 < 8; e8++) {
                int e = ty * 8 + e8;
                int k = e8 >> 1;
                float w6[6];
                #pragma unroll
                for (int m = 0; m < 6; m++) {
                    float lo, hi;
                    asm("mov.b64 {%0, %1}, %2;" : "=f"(lo), "=f"(hi) : "l"(acc[k][m]));
                    w6[m] = (e8 & 1) ? hi : lo;
                }
                int src = srcs[e], dst = dsts[e];
                float dx = dirs[e * 3 + 0], dy = dirs[e * 3 + 1], dz = dirs[e * 3 + 2];
                const float* kfr = kf + (size_t)src * FF;
                float ks1 = __ldg(kfr + tx);
                float ks2 = __ldg(kfr + 32 + tx);
                float kvx = __ldg(kfr + 64 + 3 * tx + 0);
                float kvy = __ldg(kfr + 64 + 3 * tx + 1);
                float kvz = __ldg(kfr + 64 + 3 * tx + 2);
                float dot = kvx * dx + kvy * dy + kvz * dz;
                float ms1 = w6[0] * ks1 + w6[4] * dot;
                float ms2 = w6[1] * ks2;
                float crx = kvy * dz - kvz * dy;
                float cry = kvz * dx - kvx * dz;
                float crz = kvx * dy - kvy * dx;
                float t1 = w6[3] * ks1;
                float mvx = w6[2] * kvx + t1 * dx + w6[5] * crx;
                float mvy = w6[2] * kvy + t1 * dy + w6[5] * cry;
                float mvz = w6[2] * kvz + t1 * dz + w6[5] * crz;
                if (dst != cur) {
                    if (cur >= 0) {
                        float* p = g_kfeat + (size_t)cur * FF;
                        atomicAdd(p + tx, m0 * curinv);
                        atomicAdd(p + 32 + tx, m1 * curinv);
                        atomicAdd(p + 64 + 3 * tx + 0, m2 * curinv);
                        atomicAdd(p + 64 + 3 * tx + 1, m3 * curinv);
                        atomicAdd(p + 64 + 3 * tx + 2, m4 * curinv);
                    }
                    cur = dst; curinv = invs[e];
                    m0 = ms1; m1 = ms2; m2 = mvx; m3 = mvy; m4 = mvz;
                } else {
                    m0 += ms1; m1 += ms2; m2 += mvx; m3 += mvy; m4 += mvz;
                }
            }
            if (cur >= 0) {
                float* p = g_kfeat + (size_t)cur * FF;
                atomicAdd(p + tx, m0 * curinv);
                atomicAdd(p + 32 + tx, m1 * curinv);
                atomicAdd(p + 64 + 3 * tx + 0, m2 * curinv);
                atomicAdd(p + 64 + 3 * tx + 1, m3 * curinv);
                atomicAdd(p + 64 + 3 * tx + 2, m4 * curinv);
            }
        }
    }
}

// Tensor-product heads + final weighted reduction. One warp per n, lane = channel.
__global__ __launch_bounds__(256) void tp_kernel(
    const float* __restrict__ query_f, const float* __restrict__ query_x,
    const float* __restrict__ query_w,
    const float* __restrict__ p00, const float* __restrict__ prest,
    const float* __restrict__ Ws_tp, const float* __restrict__ Wv_tp,
    float* __restrict__ out) {
    __shared__ float Wss[96 * 33];
    __shared__ float Wvs[96 * 32];
    __shared__ float s_sh[8][96];
    __shared__ float v_sh[8][96 * 3];
    __shared__ float accOut[6];
    int tid = threadIdx.x;
    int w = tid >> 5, c = tid & 31;
    int n = blockIdx.x * 8 + w;
    int t = n >> 8, q = n & 255;
    if (tid < 6) accOut[tid] = 0.0f;

    const float* kfr = g_kfeat + (size_t)n * FF;
    const float* qfr = query_f + (size_t)q * FF;
    float ks1 = kfr[c], ks2 = kfr[32 + c];
    float kvx = kfr[64 + 3 * c + 0], kvy = kfr[64 + 3 * c + 1], kvz = kfr[64 + 3 * c + 2];
    float qs1 = qfr[c], qs2 = qfr[32 + c];
    float qrx = qfr[64 + 3 * c + 0], qry = qfr[64 + 3 * c + 1], qrz = qfr[64 + 3 * c + 2];
    float R[9];
    #pragma unroll
    for (int i = 0; i < 9; i++) R[i] = __ldg(g_R + t * 9 + i);
    float qvx = R[0] * qrx + R[1] * qry + R[2] * qrz;
    float qvy = R[3] * qrx + R[4] * qry + R[5] * qrz;
    float qvz = R[6] * qrx + R[7] * qry + R[8] * qrz;

    float lin[3], ang[3];
    for (int head = 0; head < 2; head++) {
        __syncthreads();
        for (int i = tid; i < 96 * 33; i += 256) Wss[i] = Ws_tp[head * (96 * 33) + i];
        for (int i = tid; i < 96 * 32; i += 256) Wvs[i] = Wv_tp[head * (96 * 32) + i];
        __syncthreads();
        float p1 = __ldg(p00 + head * 64 + c);
        float p2 = __ldg(p00 + head * 64 + 32 + c);
        float pr0 = __ldg(prest + head * 128 + c);
        float pr1 = __ldg(prest + head * 128 + 32 + c);
        float pr2 = __ldg(prest + head * 128 + 64 + c);
        float pr3 = __ldg(prest + head * 128 + 96 + c);
        s_sh[w][c] = p1 * ks1 * qs1;
        s_sh[w][32 + c] = p2 * ks2 * qs2;
        s_sh[w][64 + c] = pr2 * (kvx * qvx + kvy * qvy + kvz * qvz);
        v_sh[w][3 * c + 0] = pr0 * kvx * qs1;
        v_sh[w][3 * c + 1] = pr0 * kvy * qs1;
        v_sh[w][3 * c + 2] = pr0 * kvz * qs1;
        v_sh[w][3 * (32 + c) + 0] = pr1 * ks1 * qvx;
        v_sh[w][3 * (32 + c) + 1] = pr1 * ks1 * qvy;
        v_sh[w][3 * (32 + c) + 2] = pr1 * ks1 * qvz;
        v_sh[w][3 * (64 + c) + 0] = pr3 * (kvy * qvz - kvz * qvy);
        v_sh[w][3 * (64 + c) + 1] = pr3 * (kvz * qvx - kvx * qvz);
        v_sh[w][3 * (64 + c) + 2] = pr3 * (kvx * qvy - kvy * qvx);
        __syncwarp();
        float sg = 0.0f, vmx = 0.0f, vmy = 0.0f, vmz = 0.0f;
        #pragma unroll 4
        for (int ch = 0; ch < 96; ch++) {
            float sv = s_sh[w][ch];
            sg += sv * Wss[ch * 33 + 1 + c];
            float wv = Wvs[ch * 32 + c];
            vmx += v_sh[w][3 * ch + 0] * wv;
            vmy += v_sh[w][3 * ch + 1] * wv;
            vmz += v_sh[w][3 * ch + 2] * wv;
        }
        float sig = 1.0f / (1.0f + __expf(-sg));
        float px = vmx * sig, py = vmy * sig, pz = vmz * sig;
        #pragma unroll
        for (int off = 16; off > 0; off >>= 1) {
            px += __shfl_xor_sync(0xffffffffu, px, off);
            py += __shfl_xor_sync(0xffffffffu, py, off);
            pz += __shfl_xor_sync(0xffffffffu, pz, off);
        }
        float sc = 1.0f / 32.0f;
        if (head == 0) { lin[0] = px * sc; lin[1] = py * sc; lin[2] = pz * sc; }
        else { ang[0] = px * sc; ang[1] = py * sc; ang[2] = pz * sc; }
        __syncwarp();
    }
    __syncthreads();
    if (c == 0) {
        float lwx = R[0] * lin[0] + R[3] * lin[1] + R[6] * lin[2];
        float lwy = R[1] * lin[0] + R[4] * lin[1] + R[7] * lin[2];
        float lwz = R[2] * lin[0] + R[5] * lin[1] + R[8] * lin[2];
        float awx = R[0] * ang[0] + R[3] * ang[1] + R[6] * ang[2];
        float awy = R[1] * ang[0] + R[4] * ang[1] + R[7] * ang[2];
        float awz = R[2] * ang[0] + R[5] * ang[1] + R[8] * ang[2];
        float qx0 = query_x[q * 3 + 0], qx1 = query_x[q * 3 + 1], qx2 = query_x[q * 3 + 2];
        float ox = qx1 * lwz - qx2 * lwy;
        float oy = qx2 * lwx - qx0 * lwz;
        float oz = qx0 * lwy - qx1 * lwx;
        float ww = query_w[q];
        atomicAdd(&accOut[0], ww * (ox + awx));
        atomicAdd(&accOut[1], ww * (oy + awy));
        atomicAdd(&accOut[2], ww * (oz + awz));
        atomicAdd(&accOut[3], ww * lwx);
        atomicAdd(&accOut[4], ww * lwy);
        atomicAdd(&accOut[5], ww * lwz);
    }
    __syncthreads();
    if (tid < 6) {
        int tt = blockIdx.x >> 5;
        int idx = (tid < 3) ? (tt * 3 + tid) : (NT * 3 + tt * 3 + (tid - 3));
        atomicAdd(out + idx, accOut[tid]);
    }
}

extern "C" void kernel_launch(void* const* d_in, const int* in_sizes, int n_in,
                              void* d_out, int out_size) {
    const float* Ts      = (const float*)d_in[0];
    const float* time_   = (const float*)d_in[1];
    const float* query_x = (const float*)d_in[2];
    const float* query_f = (const float*)d_in[3];
    const float* query_w = (const float*)d_in[4];
    const float* kx0     = (const float*)d_in[5];
    const float* kf0     = (const float*)d_in[6];
    const float* kx1     = (const float*)d_in[7];
    const float* kf1     = (const float*)d_in[8];
    const int*   es0     = (const int*)d_in[9];
    const int*   ed0     = (const int*)d_in[10];
    const int*   es1     = (const int*)d_in[11];
    const int*   ed1     = (const int*)d_in[12];
    const float* W_qt    = (const float*)d_in[13];
    const float* b_qt    = (const float*)d_in[14];
    const float* W1_r    = (const float*)d_in[15];
    const float* b1_r    = (const float*)d_in[16];
    const float* W2_r    = (const float*)d_in[17];
    const float* b2_r    = (const float*)d_in[18];
    const float* p00     = (const float*)d_in[19];
    const float* prest   = (const float*)d_in[20];
    const float* Ws_tp   = (const float*)d_in[21];
    const float* Wv_tp   = (const float*)d_in[22];
    float* out = (float*)d_out;

    // EDGE_SMEM is already in BYTES (17920 floats * 4).
    cudaFuncSetAttribute(edge_kernel, cudaFuncAttributeMaxDynamicSharedMemorySize,
                         EDGE_SMEM);

    zero_kernel<<<2048, 256>>>(out);
    hist_kernel<<<1024, 256>>>(ed0, ed1);
    scan_kernel<<<1, 1024>>>();
    prep_kernel<<<NT, 128>>>(Ts, time_, query_x, W_qt, b_qt, W1_r, b1_r);
    scatter_kernel<<<512, 256>>>(es0, ed0, es1, ed1);
    edge_kernel<<<2 * EB, 256, EDGE_SMEM>>>(kx0, kf0, kx1, kf1, W1_r, W2_r, b2_r);
    tp_kernel<<<NN / 8, 256>>>(query_f, query_x, query_w, p00, prest, Ws_tp, Wv_tp, out);
}